// round 15
// baseline (speedup 1.0000x reference)
#include <cuda_runtime.h>
#include <math.h>

#define NLEV   16
#define TSZ    524288
#define HIDDEN 64
#define FEAT   13
#define DIN    35
#define MAXDENSE 340000   // sum gs^3 for dense levels (17,23,31,43,59) = 331,757

typedef unsigned long long u64;

__device__ __forceinline__ u64 pack2(float lo, float hi) {
    u64 r; asm("mov.b64 %0, {%1, %2};" : "=l"(r) : "f"(lo), "f"(hi)); return r;
}
__device__ __forceinline__ u64 bcast2(float v) { return pack2(v, v); }
__device__ __forceinline__ u64 fma2(u64 a, u64 b, u64 c) {
    u64 d; asm("fma.rn.f32x2 %0, %1, %2, %3;" : "=l"(d) : "l"(a), "l"(b), "l"(c)); return d;
}
__device__ __forceinline__ void unpack2(u64 v, float& lo, float& hi) {
    asm("mov.b64 {%0, %1}, %2;" : "=f"(lo), "=f"(hi) : "l"(v));
}

// ---------------------------------------------------------------------------
// Weight blob: packed ulonglong2 pairs, published to __constant__ (weights are
// warp-uniform loads -> constant port, off the L1tex pipe entirely).
// ---------------------------------------------------------------------------
struct WBlob {
    ulonglong2 W0[DIN][16];      // [in][out-pairs]
    ulonglong2 W1[HIDDEN][16];
    ulonglong2 W2[HIDDEN][4];
    ulonglong2 b0[16];
    ulonglong2 b1[16];
    ulonglong2 b2[4];
};                               // 30,016 bytes < 64KB constant limit

__device__    WBlob g_blob;      // staging (written by pack_kernel)
__constant__  WBlob c_blob;      // read by sdf_kernel

// float staging for weight-norm
__device__ float g_W0T[DIN][HIDDEN];
__device__ float g_W1T[HIDDEN][HIDDEN];
__device__ float g_W2T[HIDDEN][16];
__device__ float g_b0[HIDDEN];
__device__ float g_b1[HIDDEN];
__device__ float g_b2[16];

// Paired-corner tables for dense levels: g_dense4[off+cell] = (corner(x), corner(x+1))
__device__ float4 g_dense4[MAXDENSE];

struct GridParams {
    int gs[NLEV];
    int doff[NLEV];      // float4 offset into g_dense4, or -1 if hashed
    int dtotal;
};

__global__ void prep_kernel(const float* __restrict__ V0, const float* __restrict__ g0, const float* __restrict__ b0,
                            const float* __restrict__ V1, const float* __restrict__ g1, const float* __restrict__ b1,
                            const float* __restrict__ V2, const float* __restrict__ g2, const float* __restrict__ b2)
{
    int o = threadIdx.x;
    if (o < HIDDEN) {
        float s = 0.f;
        for (int i = 0; i < DIN; i++) { float v = V0[o * DIN + i]; s += v * v; }
        float sc = g0[o] / sqrtf(s);
        for (int i = 0; i < DIN; i++) g_W0T[i][o] = V0[o * DIN + i] * sc;
        g_b0[o] = b0[o];

        s = 0.f;
        for (int i = 0; i < HIDDEN; i++) { float v = V1[o * HIDDEN + i]; s += v * v; }
        sc = g1[o] / sqrtf(s);
        for (int i = 0; i < HIDDEN; i++) g_W1T[i][o] = V1[o * HIDDEN + i] * sc;
        g_b1[o] = b1[o];
    }
    if (o < 16) {
        if (o < FEAT) {
            float s = 0.f;
            for (int i = 0; i < HIDDEN; i++) { float v = V2[o * HIDDEN + i]; s += v * v; }
            float sc = g2[o] / sqrtf(s);
            for (int i = 0; i < HIDDEN; i++) g_W2T[i][o] = V2[o * HIDDEN + i] * sc;
            g_b2[o] = b2[o];
        } else {
            for (int i = 0; i < HIDDEN; i++) g_W2T[i][o] = 0.f;
            g_b2[o] = 0.f;
        }
    }
}

__device__ __forceinline__ ulonglong2 pack4(const float* s) {
    ulonglong2 v;
    v.x = ((u64)__float_as_uint(s[1]) << 32) | (u64)__float_as_uint(s[0]);
    v.y = ((u64)__float_as_uint(s[3]) << 32) | (u64)__float_as_uint(s[2]);
    return v;
}

__global__ void pack_kernel()
{
    const int NW0 = DIN * 16, NW1 = HIDDEN * 16, NW2 = HIDDEN * 4;
    const int total = NW0 + NW1 + NW2 + 16 + 16 + 4;
    for (int e = threadIdx.x; e < total; e += blockDim.x) {
        int r = e;
        if (r < NW0) { (&g_blob.W0[0][0])[r] = pack4(&(&g_W0T[0][0])[4 * r]); continue; }
        r -= NW0;
        if (r < NW1) { (&g_blob.W1[0][0])[r] = pack4(&(&g_W1T[0][0])[4 * r]); continue; }
        r -= NW1;
        if (r < NW2) { (&g_blob.W2[0][0])[r] = pack4(&(&g_W2T[0][0])[4 * r]); continue; }
        r -= NW2;
        if (r < 16) { g_blob.b0[r] = pack4(&g_b0[4 * r]); continue; }
        r -= 16;
        if (r < 16) { g_blob.b1[r] = pack4(&g_b1[4 * r]); continue; }
        r -= 16;
        g_blob.b2[r] = pack4(&g_b2[4 * r]);
    }
}

// Build paired-corner dense tables (dense-direct levels only, gs^3 <= TSZ).
__global__ void repack_kernel(const float* __restrict__ table, GridParams gp)
{
    const float2* __restrict__ tab = (const float2*)table;
    for (int i = blockIdx.x * blockDim.x + threadIdx.x; i < gp.dtotal;
         i += gridDim.x * blockDim.x) {
        #pragma unroll
        for (int lv = 0; lv < NLEV; lv++) {
            if (gp.doff[lv] < 0) continue;
            const int gs = gp.gs[lv];
            const int ncell = gs * gs * gs;
            const int rel = i - gp.doff[lv];
            if (rel >= 0 && rel < ncell) {
                const float2 a = tab[(size_t)lv * TSZ + rel];
                const float2 b = tab[(size_t)lv * TSZ + rel + 1];
                g_dense4[i] = make_float4(a.x, a.y, b.x, b.y);
            }
        }
    }
}

// Fast softplus(100z)/100 (error audit in R8 — ~1e-6 abs on /100 output).
__device__ __forceinline__ float softplus100(float z)
{
    float x = 100.f * z;
    float t = __expf(-fabsf(x));
    return (fmaxf(x, 0.f) + __logf(1.f + t)) * 0.01f;
}

__global__ __launch_bounds__(128, 5)
void sdf_kernel(const float* __restrict__ points,
                const float* __restrict__ table,
                float* __restrict__ out,
                int n, GridParams gp)
{
    const int tid = threadIdx.x;
    const int p = blockIdx.x * 128 + tid;
    if (p >= n) return;

    const float px = points[3 * p + 0];
    const float py = points[3 * p + 1];
    const float pz = points[3 * p + 2];
    const float ux = fminf(fmaxf((px + 1.f) * 0.5f, 0.f), 1.f);
    const float uy = fminf(fmaxf((py + 1.f) * 0.5f, 0.f), 1.f);
    const float uz = fminf(fmaxf((pz + 1.f) * 0.5f, 0.f), 1.f);

    const float2* __restrict__ tab = (const float2*)table;
    const float4* __restrict__ dtab = (const float4*)g_dense4;

    // ---- gather phase: per-level features into scalar regs --------------
    float enc[2 * NLEV];
    #pragma unroll
    for (int lv = 0; lv < NLEV; lv++) {
        const int gs = gp.gs[lv];
        const float gm1 = (float)(gs - 1);
        const float fx = ux * gm1, fy = uy * gm1, fz = uz * gm1;
        int ix = (int)floorf(fx); ix = min(max(ix, 0), gs - 2);
        int iy = (int)floorf(fy); iy = min(max(iy, 0), gs - 2);
        int iz = (int)floorf(fz); iz = min(max(iz, 0), gs - 2);
        const float wx = fx - (float)ix;
        const float wy = fy - (float)iy;
        const float wz = fz - (float)iz;

        float2 f[8];   // c = i*4 + j*2 + k
        if (gp.doff[lv] >= 0) {
            const int g1 = gs, g2 = gs * gs;
            const int base = ix + g1 * iy + g2 * iz;
            const float4* __restrict__ dl = dtab + gp.doff[lv];
            const float4 q0 = __ldg(&dl[base]);
            const float4 q1 = __ldg(&dl[base + g2]);
            const float4 q2 = __ldg(&dl[base + g1]);
            const float4 q3 = __ldg(&dl[base + g1 + g2]);
            f[0] = make_float2(q0.x, q0.y); f[4] = make_float2(q0.z, q0.w);
            f[1] = make_float2(q1.x, q1.y); f[5] = make_float2(q1.z, q1.w);
            f[2] = make_float2(q2.x, q2.y); f[6] = make_float2(q2.z, q2.w);
            f[3] = make_float2(q3.x, q3.y); f[7] = make_float2(q3.z, q3.w);
        } else {
            const unsigned hx0 = (unsigned)ix,               hx1 = hx0 + 1u;
            const unsigned hy0 = (unsigned)iy * 2654435761u, hy1 = hy0 + 2654435761u;
            const unsigned hz0 = (unsigned)iz * 805459861u,  hz1 = hz0 + 805459861u;
            const unsigned M = (unsigned)(TSZ - 1);
            unsigned idxs[8];
            idxs[0] = (hx0 ^ hy0 ^ hz0) & M;
            idxs[1] = (hx0 ^ hy0 ^ hz1) & M;
            idxs[2] = (hx0 ^ hy1 ^ hz0) & M;
            idxs[3] = (hx0 ^ hy1 ^ hz1) & M;
            idxs[4] = (hx1 ^ hy0 ^ hz0) & M;
            idxs[5] = (hx1 ^ hy0 ^ hz1) & M;
            idxs[6] = (hx1 ^ hy1 ^ hz0) & M;
            idxs[7] = (hx1 ^ hy1 ^ hz1) & M;
            const float2* __restrict__ tb = tab + (size_t)lv * TSZ;
            #pragma unroll
            for (int c = 0; c < 8; c++) f[c] = __ldg(&tb[idxs[c]]);
        }

        const float ox = 1.f - wx, oy = 1.f - wy, oz = 1.f - wz;
        const float w0 = ox * oy * oz,  w1 = ox * oy * wz;
        const float w2 = ox * wy * oz,  w3 = ox * wy * wz;
        const float w4 = wx * oy * oz,  w5 = wx * oy * wz;
        const float w6 = wx * wy * oz,  w7 = wx * wy * wz;
        enc[2 * lv]     = f[0].x * w0 + f[1].x * w1 + f[2].x * w2 + f[3].x * w3
                        + f[4].x * w4 + f[5].x * w5 + f[6].x * w6 + f[7].x * w7;
        enc[2 * lv + 1] = f[0].y * w0 + f[1].y * w1 + f[2].y * w2 + f[3].y * w3
                        + f[4].y * w4 + f[5].y * w5 + f[6].y * w6 + f[7].y * w7;
    }

    // ---- layer 0: two output halves (16 u64 acc live at a time) ---------
    float h[HIDDEN];
    #pragma unroll
    for (int half = 0; half < 2; half++) {
        u64 acc[16];
        #pragma unroll
        for (int q = 0; q < 8; q++) {
            const ulonglong2 b = c_blob.b0[8 * half + q];
            acc[2 * q] = b.x; acc[2 * q + 1] = b.y;
        }
        const u64 bx = bcast2(px), by = bcast2(py), bz = bcast2(pz);
        #pragma unroll
        for (int q = 0; q < 8; q++) {
            const ulonglong2 va = c_blob.W0[0][8 * half + q];
            const ulonglong2 vb = c_blob.W0[1][8 * half + q];
            const ulonglong2 vc = c_blob.W0[2][8 * half + q];
            acc[2 * q]     = fma2(bx, va.x, acc[2 * q]);
            acc[2 * q + 1] = fma2(bx, va.y, acc[2 * q + 1]);
            acc[2 * q]     = fma2(by, vb.x, acc[2 * q]);
            acc[2 * q + 1] = fma2(by, vb.y, acc[2 * q + 1]);
            acc[2 * q]     = fma2(bz, vc.x, acc[2 * q]);
            acc[2 * q + 1] = fma2(bz, vc.y, acc[2 * q + 1]);
        }
        #pragma unroll
        for (int lv = 0; lv < NLEV; lv++) {
            const int r = 3 + 2 * lv;
            const u64 bf0 = bcast2(enc[2 * lv]), bf1 = bcast2(enc[2 * lv + 1]);
            #pragma unroll
            for (int q = 0; q < 8; q++) {
                const ulonglong2 va = c_blob.W0[r][8 * half + q];
                const ulonglong2 vb = c_blob.W0[r + 1][8 * half + q];
                acc[2 * q]     = fma2(bf0, va.x, acc[2 * q]);
                acc[2 * q + 1] = fma2(bf0, va.y, acc[2 * q + 1]);
                acc[2 * q]     = fma2(bf1, vb.x, acc[2 * q]);
                acc[2 * q + 1] = fma2(bf1, vb.y, acc[2 * q + 1]);
            }
        }
        #pragma unroll
        for (int j = 0; j < 16; j++) {
            float lo, hi; unpack2(acc[j], lo, hi);
            h[32 * half + 2 * j]     = softplus100(lo);
            h[32 * half + 2 * j + 1] = softplus100(hi);
        }
    }

    // ---- layer 1: two output halves -------------------------------------
    float h1[HIDDEN];
    #pragma unroll
    for (int half = 0; half < 2; half++) {
        u64 acc1[16];
        #pragma unroll
        for (int q = 0; q < 8; q++) {
            const ulonglong2 b = c_blob.b1[8 * half + q];
            acc1[2 * q] = b.x; acc1[2 * q + 1] = b.y;
        }
        #pragma unroll 8
        for (int i = 0; i < HIDDEN; i++) {
            const u64 hb = bcast2(h[i]);
            #pragma unroll
            for (int q = 0; q < 8; q++) {
                const ulonglong2 v = c_blob.W1[i][8 * half + q];
                acc1[2 * q]     = fma2(hb, v.x, acc1[2 * q]);
                acc1[2 * q + 1] = fma2(hb, v.y, acc1[2 * q + 1]);
            }
        }
        #pragma unroll
        for (int j = 0; j < 16; j++) {
            float lo, hi; unpack2(acc1[j], lo, hi);
            h1[32 * half + 2 * j]     = softplus100(lo);
            h1[32 * half + 2 * j + 1] = softplus100(hi);
        }
    }

    // ---- layer 2 ---------------------------------------------------------
    u64 acc2[8];
    #pragma unroll
    for (int q = 0; q < 4; q++) {
        const ulonglong2 b = c_blob.b2[q];
        acc2[2 * q] = b.x; acc2[2 * q + 1] = b.y;
    }
    #pragma unroll 8
    for (int i = 0; i < HIDDEN; i++) {
        const u64 hb = bcast2(h1[i]);
        #pragma unroll
        for (int q = 0; q < 4; q++) {
            const ulonglong2 v = c_blob.W2[i][q];
            acc2[2 * q]     = fma2(hb, v.x, acc2[2 * q]);
            acc2[2 * q + 1] = fma2(hb, v.y, acc2[2 * q + 1]);
        }
    }

    float o2[16];
    #pragma unroll
    for (int j = 0; j < 8; j++) unpack2(acc2[j], o2[2 * j], o2[2 * j + 1]);

    out[p] = o2[0];
    float* __restrict__ hout = out + n + (size_t)p * FEAT;
    #pragma unroll
    for (int j = 0; j < FEAT; j++) hout[j] = o2[j];
}

extern "C" void kernel_launch(void* const* d_in, const int* in_sizes, int n_in,
                              void* d_out, int out_size)
{
    const float* points = (const float*)d_in[0];
    const float* table  = (const float*)d_in[1];
    const float* V0 = (const float*)d_in[2];
    const float* g0 = (const float*)d_in[3];
    const float* b0 = (const float*)d_in[4];
    const float* V1 = (const float*)d_in[5];
    const float* g1 = (const float*)d_in[6];
    const float* b1 = (const float*)d_in[7];
    const float* V2 = (const float*)d_in[8];
    const float* g2 = (const float*)d_in[9];
    const float* b2 = (const float*)d_in[10];
    float* out = (float*)d_out;

    const int n = in_sizes[0] / 3;

    GridParams gp;
    const double scale = exp((log(2048.0) - log(16.0)) / 15.0);
    int run = 0;
    for (int lv = 0; lv < NLEV; lv++) {
        const int gs = (int)floor(16.0 * pow(scale, (double)lv)) + 1;
        gp.gs[lv] = gs;
        const long long ncell = (long long)gs * gs * gs;
        if (ncell <= (long long)TSZ && run + ncell <= MAXDENSE) {
            gp.doff[lv] = run;
            run += (int)ncell;
        } else {
            gp.doff[lv] = -1;
        }
    }
    gp.dtotal = run;

    prep_kernel<<<1, 64>>>(V0, g0, b0, V1, g1, b1, V2, g2, b2);
    pack_kernel<<<1, 256>>>();

    // Publish packed weights to constant memory (D2D copy, graph-capturable).
    void* blob_src = nullptr;
    cudaGetSymbolAddress(&blob_src, g_blob);
    cudaMemcpyToSymbolAsync(c_blob, blob_src, sizeof(WBlob), 0,
                            cudaMemcpyDeviceToDevice);

    repack_kernel<<<512, 256>>>(table, gp);

    const int blocks = (n + 127) / 128;
    sdf_kernel<<<blocks, 128>>>(points, table, out, n, gp);
}

// round 16
// speedup vs baseline: 1.0671x; 1.0671x over previous
#include <cuda_runtime.h>
#include <math.h>

#define NLEV   16
#define TSZ    524288
#define HIDDEN 64
#define FEAT   13
#define DIN    35
#define MAXDENSE 340000   // sum gs^3 for dense levels (17,23,31,43,59) = 331,757

typedef unsigned long long u64;

__device__ __forceinline__ u64 pack2(float lo, float hi) {
    u64 r; asm("mov.b64 %0, {%1, %2};" : "=l"(r) : "f"(lo), "f"(hi)); return r;
}
__device__ __forceinline__ u64 bcast2(float v) { return pack2(v, v); }
__device__ __forceinline__ u64 fma2(u64 a, u64 b, u64 c) {
    u64 d; asm("fma.rn.f32x2 %0, %1, %2, %3;" : "=l"(d) : "l"(a), "l"(b), "l"(c)); return d;
}
__device__ __forceinline__ void unpack2(u64 v, float& lo, float& hi) {
    asm("mov.b64 {%0, %1}, %2;" : "=f"(lo), "=f"(hi) : "l"(v));
}

// ---------------------------------------------------------------------------
// Weight staging + value-packed ulonglong2 forms (native wide type, no punning)
// ---------------------------------------------------------------------------
__device__ float g_W0T[DIN][HIDDEN];
__device__ float g_W1T[HIDDEN][HIDDEN];
__device__ float g_W2T[HIDDEN][16];
__device__ float g_b0[HIDDEN];
__device__ float g_b1[HIDDEN];
__device__ float g_b2[16];

__device__ ulonglong2 g_W0p[DIN][16];
__device__ ulonglong2 g_W1p[HIDDEN][16];
__device__ ulonglong2 g_W2p[HIDDEN][4];
__device__ ulonglong2 g_b0p[16];
__device__ ulonglong2 g_b1p[16];
__device__ ulonglong2 g_b2p[4];

// Paired-corner tables for dense levels: g_dense4[off+cell] = (corner(x), corner(x+1))
__device__ float4 g_dense4[MAXDENSE];

struct GridParams {
    int gs[NLEV];
    int doff[NLEV];      // float4 offset into g_dense4, or -1 if hashed
    int dtotal;
};

__global__ void prep_kernel(const float* __restrict__ V0, const float* __restrict__ g0, const float* __restrict__ b0,
                            const float* __restrict__ V1, const float* __restrict__ g1, const float* __restrict__ b1,
                            const float* __restrict__ V2, const float* __restrict__ g2, const float* __restrict__ b2)
{
    int o = threadIdx.x;
    if (o < HIDDEN) {
        float s = 0.f;
        for (int i = 0; i < DIN; i++) { float v = V0[o * DIN + i]; s += v * v; }
        float sc = g0[o] / sqrtf(s);
        for (int i = 0; i < DIN; i++) g_W0T[i][o] = V0[o * DIN + i] * sc;
        g_b0[o] = b0[o];

        s = 0.f;
        for (int i = 0; i < HIDDEN; i++) { float v = V1[o * HIDDEN + i]; s += v * v; }
        sc = g1[o] / sqrtf(s);
        for (int i = 0; i < HIDDEN; i++) g_W1T[i][o] = V1[o * HIDDEN + i] * sc;
        g_b1[o] = b1[o];
    }
    if (o < 16) {
        if (o < FEAT) {
            float s = 0.f;
            for (int i = 0; i < HIDDEN; i++) { float v = V2[o * HIDDEN + i]; s += v * v; }
            float sc = g2[o] / sqrtf(s);
            for (int i = 0; i < HIDDEN; i++) g_W2T[i][o] = V2[o * HIDDEN + i] * sc;
            g_b2[o] = b2[o];
        } else {
            for (int i = 0; i < HIDDEN; i++) g_W2T[i][o] = 0.f;
            g_b2[o] = 0.f;
        }
    }
}

__device__ __forceinline__ ulonglong2 pack4(const float* s) {
    ulonglong2 v;
    v.x = ((u64)__float_as_uint(s[1]) << 32) | (u64)__float_as_uint(s[0]);
    v.y = ((u64)__float_as_uint(s[3]) << 32) | (u64)__float_as_uint(s[2]);
    return v;
}

__global__ void pack_kernel()
{
    const int NW0 = DIN * 16, NW1 = HIDDEN * 16, NW2 = HIDDEN * 4;
    const int total = NW0 + NW1 + NW2 + 16 + 16 + 4;
    for (int e = threadIdx.x; e < total; e += blockDim.x) {
        int r = e;
        if (r < NW0) { (&g_W0p[0][0])[r] = pack4(&(&g_W0T[0][0])[4 * r]); continue; }
        r -= NW0;
        if (r < NW1) { (&g_W1p[0][0])[r] = pack4(&(&g_W1T[0][0])[4 * r]); continue; }
        r -= NW1;
        if (r < NW2) { (&g_W2p[0][0])[r] = pack4(&(&g_W2T[0][0])[4 * r]); continue; }
        r -= NW2;
        if (r < 16) { g_b0p[r] = pack4(&g_b0[4 * r]); continue; }
        r -= 16;
        if (r < 16) { g_b1p[r] = pack4(&g_b1[4 * r]); continue; }
        r -= 16;
        g_b2p[r] = pack4(&g_b2[4 * r]);
    }
}

// Build paired-corner dense tables (dense-direct levels only, gs^3 <= TSZ).
__global__ void repack_kernel(const float* __restrict__ table, GridParams gp)
{
    const float2* __restrict__ tab = (const float2*)table;
    for (int i = blockIdx.x * blockDim.x + threadIdx.x; i < gp.dtotal;
         i += gridDim.x * blockDim.x) {
        #pragma unroll
        for (int lv = 0; lv < NLEV; lv++) {
            if (gp.doff[lv] < 0) continue;
            const int gs = gp.gs[lv];
            const int ncell = gs * gs * gs;
            const int rel = i - gp.doff[lv];
            if (rel >= 0 && rel < ncell) {
                const float2 a = tab[(size_t)lv * TSZ + rel];
                const float2 b = tab[(size_t)lv * TSZ + rel + 1];
                g_dense4[i] = make_float4(a.x, a.y, b.x, b.y);
            }
        }
    }
}

// Fast softplus(100z)/100 (error audit in R8 — ~1e-6 abs on /100 output).
__device__ __forceinline__ float softplus100(float z)
{
    float x = 100.f * z;
    float t = __expf(-fabsf(x));
    return (fmaxf(x, 0.f) + __logf(1.f + t)) * 0.01f;
}

__global__ __launch_bounds__(128, 5)
void sdf_kernel(const float* __restrict__ points,
                const float* __restrict__ table,
                float* __restrict__ out,
                int n, GridParams gp)
{
    __shared__ ulonglong2 sW0[DIN][16];
    __shared__ ulonglong2 sW1[HIDDEN][16];
    __shared__ ulonglong2 sW2[HIDDEN][4];
    __shared__ ulonglong2 sb0[16];
    __shared__ ulonglong2 sb1[16];
    __shared__ ulonglong2 sb2[4];
    __shared__ float sStage[4][32 * FEAT];   // per-warp output staging

    const int tid = threadIdx.x;
    for (int i = tid; i < DIN * 16;    i += 128) (&sW0[0][0])[i] = (&g_W0p[0][0])[i];
    for (int i = tid; i < HIDDEN * 16; i += 128) (&sW1[0][0])[i] = (&g_W1p[0][0])[i];
    for (int i = tid; i < HIDDEN * 4;  i += 128) (&sW2[0][0])[i] = (&g_W2p[0][0])[i];
    if (tid < 16) { sb0[tid] = g_b0p[tid]; sb1[tid] = g_b1p[tid]; }
    if (tid < 4)  { sb2[tid] = g_b2p[tid]; }
    __syncthreads();

    const int wid  = tid >> 5;
    const int lane = tid & 31;
    const int p = blockIdx.x * 128 + tid;

    if (p < n) {
        const float px = points[3 * p + 0];
        const float py = points[3 * p + 1];
        const float pz = points[3 * p + 2];
        const float ux = fminf(fmaxf((px + 1.f) * 0.5f, 0.f), 1.f);
        const float uy = fminf(fmaxf((py + 1.f) * 0.5f, 0.f), 1.f);
        const float uz = fminf(fmaxf((pz + 1.f) * 0.5f, 0.f), 1.f);

        const float2* __restrict__ tab = (const float2*)table;
        const float4* __restrict__ dtab = (const float4*)g_dense4;

        // ---- gather phase: per-level features into scalar regs ----------
        float enc[2 * NLEV];
        #pragma unroll
        for (int lv = 0; lv < NLEV; lv++) {
            const int gs = gp.gs[lv];
            const float gm1 = (float)(gs - 1);
            const float fx = ux * gm1, fy = uy * gm1, fz = uz * gm1;
            int ix = (int)floorf(fx); ix = min(max(ix, 0), gs - 2);
            int iy = (int)floorf(fy); iy = min(max(iy, 0), gs - 2);
            int iz = (int)floorf(fz); iz = min(max(iz, 0), gs - 2);
            const float wx = fx - (float)ix;
            const float wy = fy - (float)iy;
            const float wz = fz - (float)iz;

            float2 f[8];   // c = i*4 + j*2 + k
            if (gp.doff[lv] >= 0) {
                const int g1 = gs, g2 = gs * gs;
                const int base = ix + g1 * iy + g2 * iz;
                const float4* __restrict__ dl = dtab + gp.doff[lv];
                const float4 q0 = __ldg(&dl[base]);
                const float4 q1 = __ldg(&dl[base + g2]);
                const float4 q2 = __ldg(&dl[base + g1]);
                const float4 q3 = __ldg(&dl[base + g1 + g2]);
                f[0] = make_float2(q0.x, q0.y); f[4] = make_float2(q0.z, q0.w);
                f[1] = make_float2(q1.x, q1.y); f[5] = make_float2(q1.z, q1.w);
                f[2] = make_float2(q2.x, q2.y); f[6] = make_float2(q2.z, q2.w);
                f[3] = make_float2(q3.x, q3.y); f[7] = make_float2(q3.z, q3.w);
            } else {
                const unsigned hx0 = (unsigned)ix,               hx1 = hx0 + 1u;
                const unsigned hy0 = (unsigned)iy * 2654435761u, hy1 = hy0 + 2654435761u;
                const unsigned hz0 = (unsigned)iz * 805459861u,  hz1 = hz0 + 805459861u;
                const unsigned M = (unsigned)(TSZ - 1);
                unsigned idxs[8];
                idxs[0] = (hx0 ^ hy0 ^ hz0) & M;
                idxs[1] = (hx0 ^ hy0 ^ hz1) & M;
                idxs[2] = (hx0 ^ hy1 ^ hz0) & M;
                idxs[3] = (hx0 ^ hy1 ^ hz1) & M;
                idxs[4] = (hx1 ^ hy0 ^ hz0) & M;
                idxs[5] = (hx1 ^ hy0 ^ hz1) & M;
                idxs[6] = (hx1 ^ hy1 ^ hz0) & M;
                idxs[7] = (hx1 ^ hy1 ^ hz1) & M;
                const float2* __restrict__ tb = tab + (size_t)lv * TSZ;
                #pragma unroll
                for (int c = 0; c < 8; c++) f[c] = __ldg(&tb[idxs[c]]);
            }

            const float ox = 1.f - wx, oy = 1.f - wy, oz = 1.f - wz;
            const float w0 = ox * oy * oz,  w1 = ox * oy * wz;
            const float w2 = ox * wy * oz,  w3 = ox * wy * wz;
            const float w4 = wx * oy * oz,  w5 = wx * oy * wz;
            const float w6 = wx * wy * oz,  w7 = wx * wy * wz;
            enc[2 * lv]     = f[0].x * w0 + f[1].x * w1 + f[2].x * w2 + f[3].x * w3
                            + f[4].x * w4 + f[5].x * w5 + f[6].x * w6 + f[7].x * w7;
            enc[2 * lv + 1] = f[0].y * w0 + f[1].y * w1 + f[2].y * w2 + f[3].y * w3
                            + f[4].y * w4 + f[5].y * w5 + f[6].y * w6 + f[7].y * w7;
        }

        // ---- layer 0: two output halves (16 u64 acc live at a time) -----
        float h[HIDDEN];
        #pragma unroll
        for (int half = 0; half < 2; half++) {
            u64 acc[16];
            #pragma unroll
            for (int q = 0; q < 8; q++) {
                const ulonglong2 b = sb0[8 * half + q];
                acc[2 * q] = b.x; acc[2 * q + 1] = b.y;
            }
            const u64 bx = bcast2(px), by = bcast2(py), bz = bcast2(pz);
            #pragma unroll
            for (int q = 0; q < 8; q++) {
                const ulonglong2 va = sW0[0][8 * half + q];
                const ulonglong2 vb = sW0[1][8 * half + q];
                const ulonglong2 vc = sW0[2][8 * half + q];
                acc[2 * q]     = fma2(bx, va.x, acc[2 * q]);
                acc[2 * q + 1] = fma2(bx, va.y, acc[2 * q + 1]);
                acc[2 * q]     = fma2(by, vb.x, acc[2 * q]);
                acc[2 * q + 1] = fma2(by, vb.y, acc[2 * q + 1]);
                acc[2 * q]     = fma2(bz, vc.x, acc[2 * q]);
                acc[2 * q + 1] = fma2(bz, vc.y, acc[2 * q + 1]);
            }
            #pragma unroll
            for (int lv = 0; lv < NLEV; lv++) {
                const int r = 3 + 2 * lv;
                const u64 bf0 = bcast2(enc[2 * lv]), bf1 = bcast2(enc[2 * lv + 1]);
                #pragma unroll
                for (int q = 0; q < 8; q++) {
                    const ulonglong2 va = sW0[r][8 * half + q];
                    const ulonglong2 vb = sW0[r + 1][8 * half + q];
                    acc[2 * q]     = fma2(bf0, va.x, acc[2 * q]);
                    acc[2 * q + 1] = fma2(bf0, va.y, acc[2 * q + 1]);
                    acc[2 * q]     = fma2(bf1, vb.x, acc[2 * q]);
                    acc[2 * q + 1] = fma2(bf1, vb.y, acc[2 * q + 1]);
                }
            }
            #pragma unroll
            for (int j = 0; j < 16; j++) {
                float lo, hi; unpack2(acc[j], lo, hi);
                h[32 * half + 2 * j]     = softplus100(lo);
                h[32 * half + 2 * j + 1] = softplus100(hi);
            }
        }

        // ---- layer 1: two output halves ---------------------------------
        float h1[HIDDEN];
        #pragma unroll
        for (int half = 0; half < 2; half++) {
            u64 acc1[16];
            #pragma unroll
            for (int q = 0; q < 8; q++) {
                const ulonglong2 b = sb1[8 * half + q];
                acc1[2 * q] = b.x; acc1[2 * q + 1] = b.y;
            }
            #pragma unroll 8
            for (int i = 0; i < HIDDEN; i++) {
                const u64 hb = bcast2(h[i]);
                #pragma unroll
                for (int q = 0; q < 8; q++) {
                    const ulonglong2 v = sW1[i][8 * half + q];
                    acc1[2 * q]     = fma2(hb, v.x, acc1[2 * q]);
                    acc1[2 * q + 1] = fma2(hb, v.y, acc1[2 * q + 1]);
                }
            }
            #pragma unroll
            for (int j = 0; j < 16; j++) {
                float lo, hi; unpack2(acc1[j], lo, hi);
                h1[32 * half + 2 * j]     = softplus100(lo);
                h1[32 * half + 2 * j + 1] = softplus100(hi);
            }
        }

        // ---- layer 2 -----------------------------------------------------
        u64 acc2[8];
        #pragma unroll
        for (int q = 0; q < 4; q++) {
            const ulonglong2 b = sb2[q];
            acc2[2 * q] = b.x; acc2[2 * q + 1] = b.y;
        }
        #pragma unroll 8
        for (int i = 0; i < HIDDEN; i++) {
            const u64 hb = bcast2(h1[i]);
            #pragma unroll
            for (int q = 0; q < 4; q++) {
                const ulonglong2 v = sW2[i][q];
                acc2[2 * q]     = fma2(hb, v.x, acc2[2 * q]);
                acc2[2 * q + 1] = fma2(hb, v.y, acc2[2 * q + 1]);
            }
        }

        float o2[16];
        #pragma unroll
        for (int j = 0; j < 8; j++) unpack2(acc2[j], o2[2 * j], o2[2 * j + 1]);

        out[p] = o2[0];
        // stage 13 h outputs per-warp (lane*13 stride, 13 coprime 32 -> conflict-free)
        #pragma unroll
        for (int j = 0; j < FEAT; j++) sStage[wid][lane * FEAT + j] = o2[j];
    }

    // warp-local coalesced store (no block barrier; warps proceed independently)
    __syncwarp();
    const int pb = blockIdx.x * 128 + wid * 32;   // warp's first point
    const int cnt = min(32, n - pb);
    if (cnt > 0) {
        float* __restrict__ dst = out + n + (size_t)pb * FEAT;
        const float* __restrict__ src = &sStage[wid][0];
        const int total = cnt * FEAT;
        for (int i = lane; i < total; i += 32) dst[i] = src[i];
    }
}

extern "C" void kernel_launch(void* const* d_in, const int* in_sizes, int n_in,
                              void* d_out, int out_size)
{
    const float* points = (const float*)d_in[0];
    const float* table  = (const float*)d_in[1];
    const float* V0 = (const float*)d_in[2];
    const float* g0 = (const float*)d_in[3];
    const float* b0 = (const float*)d_in[4];
    const float* V1 = (const float*)d_in[5];
    const float* g1 = (const float*)d_in[6];
    const float* b1 = (const float*)d_in[7];
    const float* V2 = (const float*)d_in[8];
    const float* g2 = (const float*)d_in[9];
    const float* b2 = (const float*)d_in[10];
    float* out = (float*)d_out;

    const int n = in_sizes[0] / 3;

    GridParams gp;
    const double scale = exp((log(2048.0) - log(16.0)) / 15.0);
    int run = 0;
    for (int lv = 0; lv < NLEV; lv++) {
        const int gs = (int)floor(16.0 * pow(scale, (double)lv)) + 1;
        gp.gs[lv] = gs;
        const long long ncell = (long long)gs * gs * gs;
        if (ncell <= (long long)TSZ && run + ncell <= MAXDENSE) {
            gp.doff[lv] = run;
            run += (int)ncell;
        } else {
            gp.doff[lv] = -1;
        }
    }
    gp.dtotal = run;

    prep_kernel<<<1, 64>>>(V0, g0, b0, V1, g1, b1, V2, g2, b2);
    pack_kernel<<<1, 256>>>();
    repack_kernel<<<512, 256>>>(table, gp);

    const int blocks = (n + 127) / 128;
    sdf_kernel<<<blocks, 128>>>(points, table, out, n, gp);
}

// round 17
// speedup vs baseline: 1.5145x; 1.4192x over previous
#include <cuda_runtime.h>
#include <math.h>

#define NLEV   16
#define TSZ    524288
#define HIDDEN 64
#define FEAT   13
#define DIN    35
#define MAXDENSE 340000   // sum gs^3 for dense levels (17,23,31,43,59) = 331,757

typedef unsigned long long u64;

__device__ __forceinline__ u64 pack2(float lo, float hi) {
    u64 r; asm("mov.b64 %0, {%1, %2};" : "=l"(r) : "f"(lo), "f"(hi)); return r;
}
__device__ __forceinline__ u64 bcast2(float v) { return pack2(v, v); }
__device__ __forceinline__ u64 fma2(u64 a, u64 b, u64 c) {
    u64 d; asm("fma.rn.f32x2 %0, %1, %2, %3;" : "=l"(d) : "l"(a), "l"(b), "l"(c)); return d;
}
__device__ __forceinline__ void unpack2(u64 v, float& lo, float& hi) {
    asm("mov.b64 {%0, %1}, %2;" : "=f"(lo), "=f"(hi) : "l"(v));
}

// ---------------------------------------------------------------------------
// Weight staging + value-packed ulonglong2 forms
// ---------------------------------------------------------------------------
__device__ float g_W0T[DIN][HIDDEN];
__device__ float g_W1T[HIDDEN][HIDDEN];
__device__ float g_W2T[HIDDEN][16];
__device__ float g_b0[HIDDEN];
__device__ float g_b1[HIDDEN];
__device__ float g_b2[16];

__device__ ulonglong2 g_W0p[DIN][16];
__device__ ulonglong2 g_W1p[HIDDEN][16];
__device__ ulonglong2 g_W2p[HIDDEN][4];
__device__ ulonglong2 g_b0p[16];
__device__ ulonglong2 g_b1p[16];
__device__ ulonglong2 g_b2p[4];

// Paired-corner tables for dense levels
__device__ float4 g_dense4[MAXDENSE];

struct GridParams {
    int gs[NLEV];
    int doff[NLEV];
    int dtotal;
};

__global__ void prep_kernel(const float* __restrict__ V0, const float* __restrict__ g0, const float* __restrict__ b0,
                            const float* __restrict__ V1, const float* __restrict__ g1, const float* __restrict__ b1,
                            const float* __restrict__ V2, const float* __restrict__ g2, const float* __restrict__ b2)
{
    int o = threadIdx.x;
    if (o < HIDDEN) {
        float s = 0.f;
        for (int i = 0; i < DIN; i++) { float v = V0[o * DIN + i]; s += v * v; }
        float sc = g0[o] / sqrtf(s);
        for (int i = 0; i < DIN; i++) g_W0T[i][o] = V0[o * DIN + i] * sc;
        g_b0[o] = b0[o];

        s = 0.f;
        for (int i = 0; i < HIDDEN; i++) { float v = V1[o * HIDDEN + i]; s += v * v; }
        sc = g1[o] / sqrtf(s);
        for (int i = 0; i < HIDDEN; i++) g_W1T[i][o] = V1[o * HIDDEN + i] * sc;
        g_b1[o] = b1[o];
    }
    if (o < 16) {
        if (o < FEAT) {
            float s = 0.f;
            for (int i = 0; i < HIDDEN; i++) { float v = V2[o * HIDDEN + i]; s += v * v; }
            float sc = g2[o] / sqrtf(s);
            for (int i = 0; i < HIDDEN; i++) g_W2T[i][o] = V2[o * HIDDEN + i] * sc;
            g_b2[o] = b2[o];
        } else {
            for (int i = 0; i < HIDDEN; i++) g_W2T[i][o] = 0.f;
            g_b2[o] = 0.f;
        }
    }
}

__device__ __forceinline__ ulonglong2 pack4(const float* s) {
    ulonglong2 v;
    v.x = ((u64)__float_as_uint(s[1]) << 32) | (u64)__float_as_uint(s[0]);
    v.y = ((u64)__float_as_uint(s[3]) << 32) | (u64)__float_as_uint(s[2]);
    return v;
}

__global__ void pack_kernel()
{
    const int NW0 = DIN * 16, NW1 = HIDDEN * 16, NW2 = HIDDEN * 4;
    const int total = NW0 + NW1 + NW2 + 16 + 16 + 4;
    for (int e = threadIdx.x; e < total; e += blockDim.x) {
        int r = e;
        if (r < NW0) { (&g_W0p[0][0])[r] = pack4(&(&g_W0T[0][0])[4 * r]); continue; }
        r -= NW0;
        if (r < NW1) { (&g_W1p[0][0])[r] = pack4(&(&g_W1T[0][0])[4 * r]); continue; }
        r -= NW1;
        if (r < NW2) { (&g_W2p[0][0])[r] = pack4(&(&g_W2T[0][0])[4 * r]); continue; }
        r -= NW2;
        if (r < 16) { g_b0p[r] = pack4(&g_b0[4 * r]); continue; }
        r -= 16;
        if (r < 16) { g_b1p[r] = pack4(&g_b1[4 * r]); continue; }
        r -= 16;
        g_b2p[r] = pack4(&g_b2[4 * r]);
    }
}

__global__ void repack_kernel(const float* __restrict__ table, GridParams gp)
{
    const float2* __restrict__ tab = (const float2*)table;
    for (int i = blockIdx.x * blockDim.x + threadIdx.x; i < gp.dtotal;
         i += gridDim.x * blockDim.x) {
        #pragma unroll
        for (int lv = 0; lv < NLEV; lv++) {
            if (gp.doff[lv] < 0) continue;
            const int gs = gp.gs[lv];
            const int ncell = gs * gs * gs;
            const int rel = i - gp.doff[lv];
            if (rel >= 0 && rel < ncell) {
                const float2 a = tab[(size_t)lv * TSZ + rel];
                const float2 b = tab[(size_t)lv * TSZ + rel + 1];
                g_dense4[i] = make_float4(a.x, a.y, b.x, b.y);
            }
        }
    }
}

// Fast softplus(100z)/100 (error audit in R8 — ~1e-6 abs on /100 output).
__device__ __forceinline__ float softplus100(float z)
{
    float x = 100.f * z;
    float t = __expf(-fabsf(x));
    return (fmaxf(x, 0.f) + __logf(1.f + t)) * 0.01f;
}

// One level's feature pair for one point (R13-verified math; c = i*4+j*2+k).
__device__ __forceinline__ float2 level_feat(int gs, int doff,
        float ux, float uy, float uz,
        const float2* __restrict__ tb, const float4* __restrict__ dtab)
{
    const float gm1 = (float)(gs - 1);
    const float fx = ux * gm1, fy = uy * gm1, fz = uz * gm1;
    int ix = (int)floorf(fx); ix = min(max(ix, 0), gs - 2);
    int iy = (int)floorf(fy); iy = min(max(iy, 0), gs - 2);
    int iz = (int)floorf(fz); iz = min(max(iz, 0), gs - 2);
    const float wx = fx - (float)ix;
    const float wy = fy - (float)iy;
    const float wz = fz - (float)iz;

    float2 f[8];
    if (doff >= 0) {
        const int g1 = gs, g2 = gs * gs;
        const int base = ix + g1 * iy + g2 * iz;
        const float4* __restrict__ dl = dtab + doff;
        const float4 q0 = __ldg(&dl[base]);
        const float4 q1 = __ldg(&dl[base + g2]);
        const float4 q2 = __ldg(&dl[base + g1]);
        const float4 q3 = __ldg(&dl[base + g1 + g2]);
        f[0] = make_float2(q0.x, q0.y); f[4] = make_float2(q0.z, q0.w);
        f[1] = make_float2(q1.x, q1.y); f[5] = make_float2(q1.z, q1.w);
        f[2] = make_float2(q2.x, q2.y); f[6] = make_float2(q2.z, q2.w);
        f[3] = make_float2(q3.x, q3.y); f[7] = make_float2(q3.z, q3.w);
    } else {
        const unsigned hx0 = (unsigned)ix,               hx1 = hx0 + 1u;
        const unsigned hy0 = (unsigned)iy * 2654435761u, hy1 = hy0 + 2654435761u;
        const unsigned hz0 = (unsigned)iz * 805459861u,  hz1 = hz0 + 805459861u;
        const unsigned M = (unsigned)(TSZ - 1);
        unsigned idxs[8];
        idxs[0] = (hx0 ^ hy0 ^ hz0) & M;
        idxs[1] = (hx0 ^ hy0 ^ hz1) & M;
        idxs[2] = (hx0 ^ hy1 ^ hz0) & M;
        idxs[3] = (hx0 ^ hy1 ^ hz1) & M;
        idxs[4] = (hx1 ^ hy0 ^ hz0) & M;
        idxs[5] = (hx1 ^ hy0 ^ hz1) & M;
        idxs[6] = (hx1 ^ hy1 ^ hz0) & M;
        idxs[7] = (hx1 ^ hy1 ^ hz1) & M;
        #pragma unroll
        for (int c = 0; c < 8; c++) f[c] = __ldg(&tb[idxs[c]]);
    }

    const float ox = 1.f - wx, oy = 1.f - wy, oz = 1.f - wz;
    const float w0 = ox * oy * oz,  w1 = ox * oy * wz;
    const float w2 = ox * wy * oz,  w3 = ox * wy * wz;
    const float w4 = wx * oy * oz,  w5 = wx * oy * wz;
    const float w6 = wx * wy * oz,  w7 = wx * wy * wz;
    float2 e;
    e.x = f[0].x * w0 + f[1].x * w1 + f[2].x * w2 + f[3].x * w3
        + f[4].x * w4 + f[5].x * w5 + f[6].x * w6 + f[7].x * w7;
    e.y = f[0].y * w0 + f[1].y * w1 + f[2].y * w2 + f[3].y * w3
        + f[4].y * w4 + f[5].y * w5 + f[6].y * w6 + f[7].y * w7;
    return e;
}

// Two points per thread: weight LDS amortized over 64 points/warp.
// Activations stream through per-thread smem slots (no barriers needed).
__global__ __launch_bounds__(128, 2)
void sdf_kernel(const float* __restrict__ points,
                const float* __restrict__ table,
                float* __restrict__ out,
                int n, GridParams gp)
{
    __shared__ ulonglong2 sW0[DIN][16];
    __shared__ ulonglong2 sW1[HIDDEN][16];
    __shared__ ulonglong2 sW2[HIDDEN][4];
    __shared__ ulonglong2 sb0[16];
    __shared__ ulonglong2 sb1[16];
    __shared__ ulonglong2 sb2[4];
    extern __shared__ u64 hbuf[];    // [2][32][128] u64 = 64 KB

    const int tid = threadIdx.x;
    for (int i = tid; i < DIN * 16;    i += 128) (&sW0[0][0])[i] = (&g_W0p[0][0])[i];
    for (int i = tid; i < HIDDEN * 16; i += 128) (&sW1[0][0])[i] = (&g_W1p[0][0])[i];
    for (int i = tid; i < HIDDEN * 4;  i += 128) (&sW2[0][0])[i] = (&g_W2p[0][0])[i];
    if (tid < 16) { sb0[tid] = g_b0p[tid]; sb1[tid] = g_b1p[tid]; }
    if (tid < 4)  { sb2[tid] = g_b2p[tid]; }
    __syncthreads();

    const int p0 = blockIdx.x * 256 + tid;
    if (p0 >= n) return;
    const int p1 = p0 + 128;
    const bool has1 = (p1 < n);
    const int p1c = has1 ? p1 : p0;

    const float pxa = points[3 * p0 + 0], pya = points[3 * p0 + 1], pza = points[3 * p0 + 2];
    const float pxb = points[3 * p1c + 0], pyb = points[3 * p1c + 1], pzb = points[3 * p1c + 2];
    const float uxa = fminf(fmaxf((pxa + 1.f) * 0.5f, 0.f), 1.f);
    const float uya = fminf(fmaxf((pya + 1.f) * 0.5f, 0.f), 1.f);
    const float uza = fminf(fmaxf((pza + 1.f) * 0.5f, 0.f), 1.f);
    const float uxb = fminf(fmaxf((pxb + 1.f) * 0.5f, 0.f), 1.f);
    const float uyb = fminf(fmaxf((pyb + 1.f) * 0.5f, 0.f), 1.f);
    const float uzb = fminf(fmaxf((pzb + 1.f) * 0.5f, 0.f), 1.f);

    const float2* __restrict__ tab = (const float2*)table;
    const float4* __restrict__ dtab = (const float4*)g_dense4;

    u64* __restrict__ hsA = hbuf;
    u64* __restrict__ hsB = hbuf + 32 * 128;

    // ---- layer 0: full-width accumulators for both points ---------------
    u64 accA[32], accB[32];
    #pragma unroll
    for (int q = 0; q < 16; q++) {
        const ulonglong2 b = sb0[q];
        accA[2 * q] = b.x; accA[2 * q + 1] = b.y;
        accB[2 * q] = b.x; accB[2 * q + 1] = b.y;
    }
    {
        const u64 bxa = bcast2(pxa), bya = bcast2(pya), bza = bcast2(pza);
        const u64 bxb = bcast2(pxb), byb = bcast2(pyb), bzb = bcast2(pzb);
        #pragma unroll
        for (int q = 0; q < 16; q++) {
            const ulonglong2 va = sW0[0][q];
            const ulonglong2 vb = sW0[1][q];
            const ulonglong2 vc = sW0[2][q];
            accA[2 * q]     = fma2(bxa, va.x, accA[2 * q]);
            accA[2 * q + 1] = fma2(bxa, va.y, accA[2 * q + 1]);
            accA[2 * q]     = fma2(bya, vb.x, accA[2 * q]);
            accA[2 * q + 1] = fma2(bya, vb.y, accA[2 * q + 1]);
            accA[2 * q]     = fma2(bza, vc.x, accA[2 * q]);
            accA[2 * q + 1] = fma2(bza, vc.y, accA[2 * q + 1]);
            accB[2 * q]     = fma2(bxb, va.x, accB[2 * q]);
            accB[2 * q + 1] = fma2(bxb, va.y, accB[2 * q + 1]);
            accB[2 * q]     = fma2(byb, vb.x, accB[2 * q]);
            accB[2 * q + 1] = fma2(byb, vb.y, accB[2 * q + 1]);
            accB[2 * q]     = fma2(bzb, vc.x, accB[2 * q]);
            accB[2 * q + 1] = fma2(bzb, vc.y, accB[2 * q + 1]);
        }
    }

    #pragma unroll 2
    for (int lv = 0; lv < NLEV; lv++) {
        const int gs = gp.gs[lv];
        const int doff = gp.doff[lv];
        const float2* __restrict__ tb = tab + (size_t)lv * TSZ;
        const float2 eA = level_feat(gs, doff, uxa, uya, uza, tb, dtab);
        const float2 eB = level_feat(gs, doff, uxb, uyb, uzb, tb, dtab);
        const u64 ba0 = bcast2(eA.x), ba1 = bcast2(eA.y);
        const u64 bb0 = bcast2(eB.x), bb1 = bcast2(eB.y);
        const ulonglong2* __restrict__ wr0 = &sW0[3 + 2 * lv][0];
        const ulonglong2* __restrict__ wr1 = &sW0[4 + 2 * lv][0];
        #pragma unroll
        for (int q = 0; q < 16; q++) {
            const ulonglong2 va = wr0[q], vb = wr1[q];
            accA[2 * q]     = fma2(ba0, va.x, accA[2 * q]);
            accA[2 * q + 1] = fma2(ba0, va.y, accA[2 * q + 1]);
            accA[2 * q]     = fma2(ba1, vb.x, accA[2 * q]);
            accA[2 * q + 1] = fma2(ba1, vb.y, accA[2 * q + 1]);
            accB[2 * q]     = fma2(bb0, va.x, accB[2 * q]);
            accB[2 * q + 1] = fma2(bb0, va.y, accB[2 * q + 1]);
            accB[2 * q]     = fma2(bb1, vb.x, accB[2 * q]);
            accB[2 * q + 1] = fma2(bb1, vb.y, accB[2 * q + 1]);
        }
    }

    // softplus -> h streamed to per-thread smem slots
    #pragma unroll
    for (int j = 0; j < 32; j++) {
        float lo, hi;
        unpack2(accA[j], lo, hi);
        hsA[j * 128 + tid] = pack2(softplus100(lo), softplus100(hi));
        unpack2(accB[j], lo, hi);
        hsB[j * 128 + tid] = pack2(softplus100(lo), softplus100(hi));
    }

    // ---- layer 1: input-stationary, full-width acc ----------------------
    u64 acc1A[32], acc1B[32];
    #pragma unroll
    for (int q = 0; q < 16; q++) {
        const ulonglong2 b = sb1[q];
        acc1A[2 * q] = b.x; acc1A[2 * q + 1] = b.y;
        acc1B[2 * q] = b.x; acc1B[2 * q + 1] = b.y;
    }
    #pragma unroll 2
    for (int ip = 0; ip < 32; ip++) {
        float a0, a1, c0, c1;
        unpack2(hsA[ip * 128 + tid], a0, a1);
        unpack2(hsB[ip * 128 + tid], c0, c1);
        const u64 ba0 = bcast2(a0), ba1 = bcast2(a1);
        const u64 bb0 = bcast2(c0), bb1 = bcast2(c1);
        const ulonglong2* __restrict__ w0 = &sW1[2 * ip][0];
        const ulonglong2* __restrict__ w1 = &sW1[2 * ip + 1][0];
        #pragma unroll
        for (int q = 0; q < 16; q++) {
            const ulonglong2 va = w0[q], vb = w1[q];
            acc1A[2 * q]     = fma2(ba0, va.x, acc1A[2 * q]);
            acc1A[2 * q + 1] = fma2(ba0, va.y, acc1A[2 * q + 1]);
            acc1A[2 * q]     = fma2(ba1, vb.x, acc1A[2 * q]);
            acc1A[2 * q + 1] = fma2(ba1, vb.y, acc1A[2 * q + 1]);
            acc1B[2 * q]     = fma2(bb0, va.x, acc1B[2 * q]);
            acc1B[2 * q + 1] = fma2(bb0, va.y, acc1B[2 * q + 1]);
            acc1B[2 * q]     = fma2(bb1, vb.x, acc1B[2 * q]);
            acc1B[2 * q + 1] = fma2(bb1, vb.y, acc1B[2 * q + 1]);
        }
    }

    // softplus -> h1 streamed back into the same slots (thread-local reuse)
    #pragma unroll
    for (int j = 0; j < 32; j++) {
        float lo, hi;
        unpack2(acc1A[j], lo, hi);
        hsA[j * 128 + tid] = pack2(softplus100(lo), softplus100(hi));
        unpack2(acc1B[j], lo, hi);
        hsB[j * 128 + tid] = pack2(softplus100(lo), softplus100(hi));
    }

    // ---- layer 2 ---------------------------------------------------------
    u64 acc2A[8], acc2B[8];
    #pragma unroll
    for (int q = 0; q < 4; q++) {
        const ulonglong2 b = sb2[q];
        acc2A[2 * q] = b.x; acc2A[2 * q + 1] = b.y;
        acc2B[2 * q] = b.x; acc2B[2 * q + 1] = b.y;
    }
    #pragma unroll 4
    for (int ip = 0; ip < 32; ip++) {
        float a0, a1, c0, c1;
        unpack2(hsA[ip * 128 + tid], a0, a1);
        unpack2(hsB[ip * 128 + tid], c0, c1);
        const u64 ba0 = bcast2(a0), ba1 = bcast2(a1);
        const u64 bb0 = bcast2(c0), bb1 = bcast2(c1);
        const ulonglong2* __restrict__ w0 = &sW2[2 * ip][0];
        const ulonglong2* __restrict__ w1 = &sW2[2 * ip + 1][0];
        #pragma unroll
        for (int q = 0; q < 4; q++) {
            const ulonglong2 va = w0[q], vb = w1[q];
            acc2A[2 * q]     = fma2(ba0, va.x, acc2A[2 * q]);
            acc2A[2 * q + 1] = fma2(ba0, va.y, acc2A[2 * q + 1]);
            acc2A[2 * q]     = fma2(ba1, vb.x, acc2A[2 * q]);
            acc2A[2 * q + 1] = fma2(ba1, vb.y, acc2A[2 * q + 1]);
            acc2B[2 * q]     = fma2(bb0, va.x, acc2B[2 * q]);
            acc2B[2 * q + 1] = fma2(bb0, va.y, acc2B[2 * q + 1]);
            acc2B[2 * q]     = fma2(bb1, vb.x, acc2B[2 * q]);
            acc2B[2 * q + 1] = fma2(bb1, vb.y, acc2B[2 * q + 1]);
        }
    }

    float oA[16], oB[16];
    #pragma unroll
    for (int j = 0; j < 8; j++) {
        unpack2(acc2A[j], oA[2 * j], oA[2 * j + 1]);
        unpack2(acc2B[j], oB[2 * j], oB[2 * j + 1]);
    }

    out[p0] = oA[0];
    {
        float* __restrict__ hout = out + n + (size_t)p0 * FEAT;
        #pragma unroll
        for (int j = 0; j < FEAT; j++) hout[j] = oA[j];
    }
    if (has1) {
        out[p1] = oB[0];
        float* __restrict__ hout = out + n + (size_t)p1 * FEAT;
        #pragma unroll
        for (int j = 0; j < FEAT; j++) hout[j] = oB[j];
    }
}

extern "C" void kernel_launch(void* const* d_in, const int* in_sizes, int n_in,
                              void* d_out, int out_size)
{
    const float* points = (const float*)d_in[0];
    const float* table  = (const float*)d_in[1];
    const float* V0 = (const float*)d_in[2];
    const float* g0 = (const float*)d_in[3];
    const float* b0 = (const float*)d_in[4];
    const float* V1 = (const float*)d_in[5];
    const float* g1 = (const float*)d_in[6];
    const float* b1 = (const float*)d_in[7];
    const float* V2 = (const float*)d_in[8];
    const float* g2 = (const float*)d_in[9];
    const float* b2 = (const float*)d_in[10];
    float* out = (float*)d_out;

    const int n = in_sizes[0] / 3;

    GridParams gp;
    const double scale = exp((log(2048.0) - log(16.0)) / 15.0);
    int run = 0;
    for (int lv = 0; lv < NLEV; lv++) {
        const int gs = (int)floor(16.0 * pow(scale, (double)lv)) + 1;
        gp.gs[lv] = gs;
        const long long ncell = (long long)gs * gs * gs;
        if (ncell <= (long long)TSZ && run + ncell <= MAXDENSE) {
            gp.doff[lv] = run;
            run += (int)ncell;
        } else {
            gp.doff[lv] = -1;
        }
    }
    gp.dtotal = run;

    prep_kernel<<<1, 64>>>(V0, g0, b0, V1, g1, b1, V2, g2, b2);
    pack_kernel<<<1, 256>>>();
    repack_kernel<<<512, 256>>>(table, gp);

    const int HBYTES = 2 * 32 * 128 * (int)sizeof(u64);   // 64 KB
    cudaFuncSetAttribute(sdf_kernel,
                         cudaFuncAttributeMaxDynamicSharedMemorySize, HBYTES);

    const int blocks = (n + 255) / 256;
    sdf_kernel<<<blocks, 128, HBYTES>>>(points, table, out, n, gp);
}